// round 7
// baseline (speedup 1.0000x reference)
#include <cuda_runtime.h>
#include <cstdint>

// Problem constants
#define NN   50000
#define HID  128
#define NC   8
#define NS   5
#define NK   16
#define TILE 64                 // nodes per CTA tile
#define T1   256                // stage-1 block size
#define NTILES ((NN + TILE - 1) / TILE)   // 782
#define XPAD 129                // padded row stride (in 8B units) for dup buffers

// probs[n][c] = softmax(mlp(feats[n])) scratch; 1.6MB -> L2-resident for stage 2
__device__ float g_probs[NN * NC];

// ---------------------------------------------------------------------------
// SMEM layout (bytes)
// ---------------------------------------------------------------------------
#define OFF_W1   0                       // 128x128 f32 = 65536
#define OFF_XD   65536                   // 64 x 129 ull (x-dup, reused as h-dup) = 66048
#define OFF_W2D  131584                  // 4 x 129 float2 (paired W2) = 4128
#define OFF_B1   135712                  // 128 f32
#define OFF_B2   136224                  // 8 f32
#define SMEM_TOTAL 136320

__device__ __forceinline__ unsigned long long pack_dup(float v) {
    uint32_t b = __float_as_uint(v);
    return (unsigned long long)b | ((unsigned long long)b << 32);
}
__device__ __forceinline__ float lo_f(unsigned long long p) {
    return __uint_as_float((uint32_t)p);
}
__device__ __forceinline__ float hi_f(unsigned long long p) {
    return __uint_as_float((uint32_t)(p >> 32));
}
__device__ __forceinline__ void fma2(unsigned long long& acc,
                                     unsigned long long a,
                                     unsigned long long b) {
    asm("fma.rn.f32x2 %0, %1, %2, %0;" : "+l"(acc) : "l"(a), "l"(b));
}

// ---------------------------------------------------------------------------
// Stage 1: probs = softmax(relu(feats@W1+b1)@W2+b2), packed-f32x2 SIMT GEMM.
// One CTA per 64-node tile, 256 threads.
//   Layer 1: warp w owns nodes w*8..w*8+7; lane jt owns cols 4jt..4jt+3 as
//   two f32x2 pairs. Per k: 1 LDS.128 (W pairs) + 8 broadcast LDS.64 (x-dup)
//   -> 16 FFMA2. FMA-pipe bound at 2x the scalar-FFMA ceiling.
//   Layer 2: h duplicated into the (reused) dup buffer; thread (n, p) does a
//   128-long f32x2 dot for class pair (2p, 2p+1); 4-lane shfl softmax.
// ---------------------------------------------------------------------------
__global__ __launch_bounds__(T1, 1)
void mlp_probs_kernel(const float* __restrict__ feats,
                      const float* __restrict__ W1,
                      const float* __restrict__ b1,
                      const float* __restrict__ W2,
                      const float* __restrict__ b2)
{
    extern __shared__ char smem[];
    float* W1s = (float*)(smem + OFF_W1);
    unsigned long long* xd = (unsigned long long*)(smem + OFF_XD);   // x-dup / h-dup
    float2* w2d = (float2*)(smem + OFF_W2D);
    float* b1s = (float*)(smem + OFF_B1);
    float* b2s = (float*)(smem + OFF_B2);

    const int tid = threadIdx.x;
    const int node0 = blockIdx.x * TILE;

    // ---- prologue: weights/biases ----
    {
        const float4* src = (const float4*)W1;
        float4* dst = (float4*)W1s;
        #pragma unroll
        for (int r = 0; r < 16; r++) dst[tid + 256 * r] = src[tid + 256 * r];
    }
    // W2 paired: w2d[p*XPAD + j] = (W2[j][2p], W2[j][2p+1]); 512 entries
    #pragma unroll
    for (int r = 0; r < 2; r++) {
        int v = tid + 256 * r;            // 0..511
        int j = v >> 2, p = v & 3;
        w2d[p * XPAD + j] = make_float2(W2[j * NC + 2 * p], W2[j * NC + 2 * p + 1]);
    }
    if (tid < HID) b1s[tid] = b1[tid];
    if (tid < NC)  b2s[tid] = b2[tid];

    // ---- prologue: feature tile, duplicated (x,x) pairs ----
    {
        const float4* fsrc = (const float4*)feats;
        #pragma unroll
        for (int it = 0; it < 8; it++) {
            int g = tid + 256 * it;       // 0..2047
            int r  = g >> 5;              // local node
            int c4 = g & 31;              // float4 within row
            int gn = node0 + r;
            float4 v = (gn < NN) ? fsrc[(size_t)gn * 32 + c4]
                                 : make_float4(0.f, 0.f, 0.f, 0.f);
            unsigned long long* row = xd + (size_t)r * XPAD + c4 * 4;
            row[0] = pack_dup(v.x);
            row[1] = pack_dup(v.y);
            row[2] = pack_dup(v.z);
            row[3] = pack_dup(v.w);
        }
    }
    __syncthreads();

    // ---- layer 1: 8 nodes x 4 cols per thread, f32x2 ----
    const int jt = tid & 31;              // column group
    const int w  = tid >> 5;              // warp id -> node group
    const unsigned long long* xrow = xd + (size_t)(w * 8) * XPAD;

    unsigned long long acc[8][2];
    #pragma unroll
    for (int t = 0; t < 8; t++) { acc[t][0] = 0ull; acc[t][1] = 0ull; }

    #pragma unroll 4
    for (int i = 0; i < HID; i++) {
        const longlong2 wp = *(const longlong2*)(W1s + i * HID + 4 * jt);
        const unsigned long long w0 = (unsigned long long)wp.x;
        const unsigned long long w1 = (unsigned long long)wp.y;
        #pragma unroll
        for (int t = 0; t < 8; t++) {
            const unsigned long long xv = xrow[(size_t)t * XPAD + i];
            fma2(acc[t][0], w0, xv);
            fma2(acc[t][1], w1, xv);
        }
    }

    // bias + relu, then store duplicated h into the same buffer (cols are
    // disjoint per lane, rows disjoint per warp -> no sync needed before
    // overwrite of this thread's own region; but x of OTHER threads' region is
    // still being read, so we must sync first.
    const float4 bv = *(const float4*)(b1s + 4 * jt);
    float hvals[8][4];
    #pragma unroll
    for (int t = 0; t < 8; t++) {
        hvals[t][0] = fmaxf(lo_f(acc[t][0]) + bv.x, 0.f);
        hvals[t][1] = fmaxf(hi_f(acc[t][0]) + bv.y, 0.f);
        hvals[t][2] = fmaxf(lo_f(acc[t][1]) + bv.z, 0.f);
        hvals[t][3] = fmaxf(hi_f(acc[t][1]) + bv.w, 0.f);
    }
    __syncthreads();   // everyone done reading x-dup
    #pragma unroll
    for (int t = 0; t < 8; t++) {
        unsigned long long* hrow = xd + (size_t)(w * 8 + t) * XPAD + 4 * jt;
        hrow[0] = pack_dup(hvals[t][0]);
        hrow[1] = pack_dup(hvals[t][1]);
        hrow[2] = pack_dup(hvals[t][2]);
        hrow[3] = pack_dup(hvals[t][3]);
    }
    __syncthreads();

    // ---- layer 2 + softmax: thread (n = tid>>2, p = tid&3) ----
    {
        const int n = tid >> 2;
        const int p = tid & 3;
        const unsigned long long* hrow = xd + (size_t)n * XPAD;
        const unsigned long long* wrow = (const unsigned long long*)(w2d + (size_t)p * XPAD);
        unsigned long long a2 = 0ull;
        #pragma unroll 8
        for (int j = 0; j < HID; j++)
            fma2(a2, hrow[j], wrow[j]);

        float o0 = lo_f(a2) + b2s[2 * p];
        float o1 = hi_f(a2) + b2s[2 * p + 1];

        // softmax over 8 classes spread across 4 lanes (pairs)
        float m = fmaxf(o0, o1);
        m = fmaxf(m, __shfl_xor_sync(0xffffffffu, m, 1));
        m = fmaxf(m, __shfl_xor_sync(0xffffffffu, m, 2));
        float e0 = __expf(o0 - m);
        float e1 = __expf(o1 - m);
        float s = e0 + e1;
        s += __shfl_xor_sync(0xffffffffu, s, 1);
        s += __shfl_xor_sync(0xffffffffu, s, 2);
        const float inv = 1.f / s;

        const int gn = node0 + n;
        if (gn < NN)
            *(float2*)(g_probs + (size_t)gn * NC + 2 * p) = make_float2(e0 * inv, e1 * inv);
    }
}

// ---------------------------------------------------------------------------
// Stage 2: gather/aggregate. 4 threads per node, float2 per thread (2 classes).
// int4 index loads (4 idx per LDG) cut LSU issue ~2.5x vs R3; L1-wavefront
// floor (one per gathered 32B row) unchanged. probs (1.6MB) is L2-resident.
// ---------------------------------------------------------------------------
__global__ __launch_bounds__(256)
void aggregate_kernel(const int* __restrict__ nei,
                      const float* __restrict__ attention,
                      const float* __restrict__ alpha,
                      float* __restrict__ out)
{
    const int t = blockIdx.x * blockDim.x + threadIdx.x;
    const int n = t >> 2;
    const int q = t & 3;          // class pair: classes 2q, 2q+1
    if (n >= NN) return;

    // softmax over 5 scheme-attention logits (broadcast loads)
    float a[NS];
    #pragma unroll
    for (int s = 0; s < NS; s++) a[s] = attention[n * NS + s];
    float m = a[0];
    #pragma unroll
    for (int s = 1; s < NS; s++) m = fmaxf(m, a[s]);
    float asum = 0.f;
    #pragma unroll
    for (int s = 0; s < NS; s++) { a[s] = __expf(a[s] - m); asum += a[s]; }
    const float inv_asum = 1.f / asum;

    float ax = 0.f, ay = 0.f;
    #pragma unroll
    for (int s = 0; s < NS; s++) {
        const int4* nb = (const int4*)(nei + ((size_t)s * NN + n) * NK);
        float sx = 0.f, sy = 0.f;
        #pragma unroll
        for (int i = 0; i < 4; i++) {
            const int4 id4 = __ldg(&nb[i]);
            float2 p0 = ((const float2*)(g_probs + (size_t)id4.x * NC))[q];
            float2 p1 = ((const float2*)(g_probs + (size_t)id4.y * NC))[q];
            float2 p2 = ((const float2*)(g_probs + (size_t)id4.z * NC))[q];
            float2 p3 = ((const float2*)(g_probs + (size_t)id4.w * NC))[q];
            sx += (p0.x + p1.x) + (p2.x + p3.x);
            sy += (p0.y + p1.y) + (p2.y + p3.y);
        }
        const float wgt = a[s] * inv_asum;
        ax = fmaf(wgt, sx, ax);
        ay = fmaf(wgt, sy, ay);
    }
    ax *= (1.f / (float)NK);
    ay *= (1.f / (float)NK);

    const float g = 1.f / (1.f + __expf(-alpha[n]));
    const float2 sp = ((const float2*)(g_probs + (size_t)n * NC))[q];
    float2 o;
    o.x = g * sp.x + (1.f - g) * ax;
    o.y = g * sp.y + (1.f - g) * ay;
    ((float2*)out)[n * 4 + q] = o;
}

// ---------------------------------------------------------------------------
// Launch. Inputs: sc_nei i32[5*50000*16], feats f32[50000*128], W1 f32[128*128],
// b1 f32[128], W2 f32[128*8], b2 f32[8], alpha f32[50000], attention f32[50000*5].
// Output f32[50000*8].
// ---------------------------------------------------------------------------
extern "C" void kernel_launch(void* const* d_in, const int* in_sizes, int n_in,
                              void* d_out, int out_size)
{
    const int*   sc_nei    = (const int*)  d_in[0];
    const float* feats     = (const float*)d_in[1];
    const float* W1        = (const float*)d_in[2];
    const float* b1        = (const float*)d_in[3];
    const float* W2        = (const float*)d_in[4];
    const float* b2        = (const float*)d_in[5];
    const float* alpha     = (const float*)d_in[6];
    const float* attention = (const float*)d_in[7];
    float*       out       = (float*)d_out;

    cudaFuncSetAttribute(mlp_probs_kernel,
                         cudaFuncAttributeMaxDynamicSharedMemorySize,
                         SMEM_TOTAL);

    mlp_probs_kernel<<<NTILES, T1, SMEM_TOTAL>>>(feats, W1, b1, W2, b2);

    const int agg_threads = NN * 4;                 // 200000
    aggregate_kernel<<<(agg_threads + 255) / 256, 256>>>(sc_nei, attention, alpha, out);
}

// round 9
// speedup vs baseline: 1.1318x; 1.1318x over previous
#include <cuda_runtime.h>
#include <cstdint>

// Problem constants
#define NN   50000
#define HID  128
#define NC   8
#define NS   5
#define NK   16
#define TILE 32                 // nodes per CTA tile
#define T1   256                // stage-1 block size
#define NTILES ((NN + TILE - 1) / TILE)   // 1563
#define GRID1 296               // persistent CTAs = 2 * 148 SMs
#define HS_PAD 132              // padded h row stride (floats)

// probs[n][c] = softmax(mlp(feats[n])) scratch; 1.6MB -> L2-resident for stage 2
__device__ float g_probs[NN * NC];

// ---------------------------------------------------------------------------
// SMEM layout (bytes). Total ~100.5KB -> 2 CTAs/SM (201KB < 227KB).
// xd region (32KB) holds duplicated-x (ull) during layer 1, then is reused as
// the layer-2 h buffer (float, stride HS_PAD).
// ---------------------------------------------------------------------------
#define OFF_W1   0                       // 128x128 f32 = 65536
#define OFF_XD   65536                   // 32 nodes x 128 ull = 32768
#define OFF_W2   98304                   // 128x8 f32 = 4096
#define OFF_B1   102400                  // 128 f32 = 512
#define OFF_B2   102912                  // 8 f32 = 32
#define SMEM_TOTAL 102944

typedef unsigned long long ull;

__device__ __forceinline__ ull pack_dup(float v) {
    uint32_t b = __float_as_uint(v);
    return (ull)b | ((ull)b << 32);
}
__device__ __forceinline__ float lo_f(ull p) { return __uint_as_float((uint32_t)p); }
__device__ __forceinline__ float hi_f(ull p) { return __uint_as_float((uint32_t)(p >> 32)); }
__device__ __forceinline__ void fma2(ull& acc, ull a, ull b) {
    asm("fma.rn.f32x2 %0, %1, %2, %0;" : "+l"(acc) : "l"(a), "l"(b));
}

// ---------------------------------------------------------------------------
// Stage 1: probs = softmax(relu(feats@W1+b1)@W2+b2).
// Persistent blocks (296), grid-stride over 32-node tiles, 2 CTAs/SM.
// Layer 1 (f32x2): thread (jt=tid&31, ng=tid>>5) computes cols 4jt..4jt+3
// (= f32x2 pairs 2jt,2jt+1) for nodes 4ng..4ng+3. Per k: 1 LDS.128 (W pair)
// + 4 broadcast LDS.64 (x-dup) -> 8 FFMA2. FMA-pipe bound at 2x scalar rate.
// Layer 2: scalar, thread per (node, class), 8-lane shfl softmax (R3-proven).
// ---------------------------------------------------------------------------
__global__ __launch_bounds__(T1, 2)
void mlp_probs_kernel(const float* __restrict__ feats,
                      const float* __restrict__ W1,
                      const float* __restrict__ b1,
                      const float* __restrict__ W2,
                      const float* __restrict__ b2)
{
    extern __shared__ char smem[];
    float* W1s = (float*)(smem + OFF_W1);
    ull*   xd  = (ull*)  (smem + OFF_XD);     // x-dup during layer 1
    float* hsf = (float*)(smem + OFF_XD);     // h buffer during layer 2 (reuse)
    float* W2s = (float*)(smem + OFF_W2);
    float* b1s = (float*)(smem + OFF_B1);
    float* b2s = (float*)(smem + OFF_B2);

    const int tid = threadIdx.x;

    // ---- weights/biases: once per block ----
    {
        const float4* src = (const float4*)W1;
        float4* dst = (float4*)W1s;
        #pragma unroll
        for (int r = 0; r < 16; r++) dst[tid + 256 * r] = src[tid + 256 * r];
    }
    ((float4*)W2s)[tid] = ((const float4*)W2)[tid];   // 1024 floats
    if (tid < HID) b1s[tid] = b1[tid];
    if (tid < NC)  b2s[tid] = b2[tid];
    // (first in-loop __syncthreads covers these before use)

    const int jt = tid & 31;    // column group: cols 4jt..4jt+3
    const int ng = tid >> 5;    // node group:  nodes 4ng..4ng+3
    const int n2 = tid >> 3;    // layer-2 node within tile
    const int cc = tid & 7;     // layer-2 class

    for (int tile = blockIdx.x; tile < NTILES; tile += GRID1) {
        const int node0 = tile * TILE;

        // ---- load 32 feature rows, duplicated (x,x) f32x2 pairs ----
        {
            const float4* fsrc = (const float4*)feats;
            #pragma unroll
            for (int it = 0; it < 4; it++) {
                int g = tid + 256 * it;       // 0..1023
                int r  = g >> 5;              // local node
                int c4 = g & 31;              // float4 within row
                int gn = node0 + r;
                float4 v = (gn < NN) ? fsrc[(size_t)gn * 32 + c4]
                                     : make_float4(0.f, 0.f, 0.f, 0.f);
                ull* row = xd + (size_t)r * HID + c4 * 4;
                row[0] = pack_dup(v.x);
                row[1] = pack_dup(v.y);
                row[2] = pack_dup(v.z);
                row[3] = pack_dup(v.w);
            }
        }
        __syncthreads();

        // ---- layer 1: 4 nodes x 4 cols per thread, f32x2 ----
        ull acc[4][2];
        #pragma unroll
        for (int t = 0; t < 4; t++) { acc[t][0] = 0ull; acc[t][1] = 0ull; }

        const ull* xr = xd + (size_t)(ng * 4) * HID;
        #pragma unroll 4
        for (int i = 0; i < HID; i++) {
            const ulonglong2 wp = *(const ulonglong2*)(W1s + i * HID + 4 * jt);
            const ull x0 = xr[i];
            const ull x1 = xr[HID + i];
            const ull x2 = xr[2 * HID + i];
            const ull x3 = xr[3 * HID + i];
            fma2(acc[0][0], wp.x, x0); fma2(acc[0][1], wp.y, x0);
            fma2(acc[1][0], wp.x, x1); fma2(acc[1][1], wp.y, x1);
            fma2(acc[2][0], wp.x, x2); fma2(acc[2][1], wp.y, x2);
            fma2(acc[3][0], wp.x, x3); fma2(acc[3][1], wp.y, x3);
        }

        // bias + relu
        const float4 bv = *(const float4*)(b1s + 4 * jt);
        float hv[4][4];
        #pragma unroll
        for (int t = 0; t < 4; t++) {
            hv[t][0] = fmaxf(lo_f(acc[t][0]) + bv.x, 0.f);
            hv[t][1] = fmaxf(hi_f(acc[t][0]) + bv.y, 0.f);
            hv[t][2] = fmaxf(lo_f(acc[t][1]) + bv.z, 0.f);
            hv[t][3] = fmaxf(hi_f(acc[t][1]) + bv.w, 0.f);
        }
        __syncthreads();   // all reads of xd done -> safe to overwrite as hsf

        #pragma unroll
        for (int t = 0; t < 4; t++)
            *(float4*)(hsf + (size_t)(ng * 4 + t) * HS_PAD + 4 * jt) =
                make_float4(hv[t][0], hv[t][1], hv[t][2], hv[t][3]);
        __syncthreads();

        // ---- layer 2 + softmax: thread per (node, class) ----
        float o = b2s[cc];
        const float* hr = hsf + (size_t)n2 * HS_PAD;
        #pragma unroll 8
        for (int j = 0; j < HID; j++)
            o = fmaf(hr[j], W2s[j * NC + cc], o);

        float m = o;
        #pragma unroll
        for (int d = 1; d < NC; d <<= 1)
            m = fmaxf(m, __shfl_xor_sync(0xffffffffu, m, d));
        const float e = __expf(o - m);
        float ssum = e;
        #pragma unroll
        for (int d = 1; d < NC; d <<= 1)
            ssum += __shfl_xor_sync(0xffffffffu, ssum, d);

        const int gn = node0 + n2;
        if (gn < NN)
            g_probs[(size_t)gn * NC + cc] = e / ssum;
        __syncthreads();   // protect hsf/xd before next tile
    }
}

// ---------------------------------------------------------------------------
// Stage 2: gather/aggregate. 4 threads per node, float2 per thread (2 classes);
// the 4 lanes of a node coalesce each gathered 32B probs row into one sector.
// int4 index loads (4 idx per LDG). Block=128 -> grid 1563 smooths the
// block-per-SM quantization that capped occupancy at 53.7% in R7.
// ---------------------------------------------------------------------------
__global__ __launch_bounds__(128)
void aggregate_kernel(const int* __restrict__ nei,
                      const float* __restrict__ attention,
                      const float* __restrict__ alpha,
                      float* __restrict__ out)
{
    const int t = blockIdx.x * blockDim.x + threadIdx.x;
    const int n = t >> 2;
    const int q = t & 3;          // class pair: classes 2q, 2q+1
    if (n >= NN) return;

    // softmax over 5 scheme-attention logits (broadcast loads)
    float a[NS];
    #pragma unroll
    for (int s = 0; s < NS; s++) a[s] = attention[n * NS + s];
    float m = a[0];
    #pragma unroll
    for (int s = 1; s < NS; s++) m = fmaxf(m, a[s]);
    float asum = 0.f;
    #pragma unroll
    for (int s = 0; s < NS; s++) { a[s] = __expf(a[s] - m); asum += a[s]; }
    const float inv_asum = 1.f / asum;

    float ax = 0.f, ay = 0.f;
    #pragma unroll
    for (int s = 0; s < NS; s++) {
        const int4* nb = (const int4*)(nei + ((size_t)s * NN + n) * NK);
        float sx = 0.f, sy = 0.f;
        #pragma unroll
        for (int i = 0; i < 4; i++) {
            const int4 id4 = __ldg(&nb[i]);
            float2 p0 = ((const float2*)(g_probs + (size_t)id4.x * NC))[q];
            float2 p1 = ((const float2*)(g_probs + (size_t)id4.y * NC))[q];
            float2 p2 = ((const float2*)(g_probs + (size_t)id4.z * NC))[q];
            float2 p3 = ((const float2*)(g_probs + (size_t)id4.w * NC))[q];
            sx += (p0.x + p1.x) + (p2.x + p3.x);
            sy += (p0.y + p1.y) + (p2.y + p3.y);
        }
        const float wgt = a[s] * inv_asum;
        ax = fmaf(wgt, sx, ax);
        ay = fmaf(wgt, sy, ay);
    }
    ax *= (1.f / (float)NK);
    ay *= (1.f / (float)NK);

    const float g = 1.f / (1.f + __expf(-alpha[n]));
    const float2 sp = ((const float2*)(g_probs + (size_t)n * NC))[q];
    float2 o;
    o.x = g * sp.x + (1.f - g) * ax;
    o.y = g * sp.y + (1.f - g) * ay;
    ((float2*)out)[n * 4 + q] = o;
}

// ---------------------------------------------------------------------------
// Launch. Inputs: sc_nei i32[5*50000*16], feats f32[50000*128], W1 f32[128*128],
// b1 f32[128], W2 f32[128*8], b2 f32[8], alpha f32[50000], attention f32[50000*5].
// Output f32[50000*8].
// ---------------------------------------------------------------------------
extern "C" void kernel_launch(void* const* d_in, const int* in_sizes, int n_in,
                              void* d_out, int out_size)
{
    const int*   sc_nei    = (const int*)  d_in[0];
    const float* feats     = (const float*)d_in[1];
    const float* W1        = (const float*)d_in[2];
    const float* b1        = (const float*)d_in[3];
    const float* W2        = (const float*)d_in[4];
    const float* b2        = (const float*)d_in[5];
    const float* alpha     = (const float*)d_in[6];
    const float* attention = (const float*)d_in[7];
    float*       out       = (float*)d_out;

    cudaFuncSetAttribute(mlp_probs_kernel,
                         cudaFuncAttributeMaxDynamicSharedMemorySize,
                         SMEM_TOTAL);

    mlp_probs_kernel<<<GRID1, T1, SMEM_TOTAL>>>(feats, W1, b1, W2, b2);

    const int agg_threads = NN * 4;                 // 200000
    aggregate_kernel<<<(agg_threads + 127) / 128, 128>>>(sc_nei, attention, alpha, out);
}

// round 10
// speedup vs baseline: 1.7226x; 1.5220x over previous
#include <cuda_runtime.h>
#include <cuda_bf16.h>
#include <cstdint>

// Problem constants
#define NN   50000
#define HID  128
#define NC   8
#define NS   5
#define NK   16
#define TM   64                          // nodes per tile
#define NT2  ((NN + TM - 1) / TM)        // 782 tiles
#define GRID1 296                        // persistent CTAs, 2 per SM

// probs[n][c] scratch; 1.6MB -> L2-resident for stage 2
__device__ float g_probs[NN * NC];

// ---------------------------------------------------------------------------
// SMEM layout (bytes). W1 split-bf16 images stored [k][n] (native, .trans-fed),
// A images [m][k]. Rows are 256B = 16 chunks of 16B; chunk index XOR-swizzled
// with (row & 7) for conflict-free ldmatrix.
// ---------------------------------------------------------------------------
#define OFF_BH   0                        // 128x128 bf16 = 32768
#define OFF_BL   32768
#define OFF_AH   65536                    // 64x128 bf16 = 16384
#define OFF_AL   81920
#define OFF_W2   98304                    // 128x8 f32 = 4096
#define OFF_B1   102400                   // 128 f32
#define OFF_B2   102912                   // 8 f32 (+pad)
#define OFF_PART 103040                   // 64x8 f32 = 2048
#define SMEM_TOTAL 105088

__device__ __forceinline__ uint32_t smem_u32(const void* p) {
    uint32_t a;
    asm("{ .reg .u64 t; cvta.to.shared.u64 t, %1; cvt.u32.u64 %0, t; }" : "=r"(a) : "l"(p));
    return a;
}
__device__ __forceinline__ void ldsm4(uint32_t& r0, uint32_t& r1, uint32_t& r2, uint32_t& r3,
                                      uint32_t addr) {
    asm volatile("ldmatrix.sync.aligned.m8n8.x4.shared.b16 {%0,%1,%2,%3}, [%4];"
                 : "=r"(r0), "=r"(r1), "=r"(r2), "=r"(r3) : "r"(addr));
}
__device__ __forceinline__ void ldsm4t(uint32_t& r0, uint32_t& r1, uint32_t& r2, uint32_t& r3,
                                       uint32_t addr) {
    asm volatile("ldmatrix.sync.aligned.m8n8.x4.trans.shared.b16 {%0,%1,%2,%3}, [%4];"
                 : "=r"(r0), "=r"(r1), "=r"(r2), "=r"(r3) : "r"(addr));
}
__device__ __forceinline__ void mma_bf16(float* d,
                                         uint32_t a0, uint32_t a1, uint32_t a2, uint32_t a3,
                                         uint32_t b0, uint32_t b1) {
    asm("mma.sync.aligned.m16n8k16.row.col.f32.bf16.bf16.f32 "
        "{%0,%1,%2,%3}, {%4,%5,%6,%7}, {%8,%9}, {%0,%1,%2,%3};"
        : "+f"(d[0]), "+f"(d[1]), "+f"(d[2]), "+f"(d[3])
        : "r"(a0), "r"(a1), "r"(a2), "r"(a3), "r"(b0), "r"(b1));
}
// Split (x,y) into packed-bf16 hi pair and lo (residual) pair.
__device__ __forceinline__ void split2(float x, float y, uint32_t& hi, uint32_t& lo) {
    __nv_bfloat16 hx = __float2bfloat16(x), hy = __float2bfloat16(y);
    __nv_bfloat16 lx = __float2bfloat16(x - __bfloat162float(hx));
    __nv_bfloat16 ly = __float2bfloat16(y - __bfloat162float(hy));
    hi = (uint32_t)__bfloat16_as_ushort(hx) | ((uint32_t)__bfloat16_as_ushort(hy) << 16);
    lo = (uint32_t)__bfloat16_as_ushort(lx) | ((uint32_t)__bfloat16_as_ushort(ly) << 16);
}

// ---------------------------------------------------------------------------
// Stage 1: probs = softmax(relu(feats@W1+b1)@W2+b2) via HMMA split-bf16 (3-pass).
// 8 warps: mi = w&3 (16 M-rows each), ni = w>>2 (64 N-cols each).
// Layer 2 reuses the layer-1 D fragments directly as mma A fragments.
// ---------------------------------------------------------------------------
__global__ __launch_bounds__(256, 2)
void mlp_tc_kernel(const float* __restrict__ feats,
                   const float* __restrict__ W1,
                   const float* __restrict__ b1,
                   const float* __restrict__ W2,
                   const float* __restrict__ b2)
{
    extern __shared__ char smem[];
    const uint32_t sb = smem_u32(smem);
    const int tid  = threadIdx.x;
    const int lane = tid & 31;
    const int w    = tid >> 5;
    const int mi   = w & 3;
    const int ni   = w >> 2;

    float* W2s  = (float*)(smem + OFF_W2);
    float* b1s  = (float*)(smem + OFF_B1);
    float* b2s  = (float*)(smem + OFF_B2);
    float* part = (float*)(smem + OFF_PART);

    // ---- prologue: W1 -> Bh/Bl ([k][n] bf16, swizzled), W2, biases ----
    {
        const float4* w1v = (const float4*)W1;
        #pragma unroll
        for (int r = 0; r < 16; r++) {
            int idx = tid + 256 * r;           // 0..4095
            int k = idx >> 5, q = idx & 31;    // row k, float4 q
            float4 v = w1v[idx];
            uint32_t hp0, lp0, hp1, lp1;
            split2(v.x, v.y, hp0, lp0);
            split2(v.z, v.w, hp1, lp1);
            uint32_t off = (uint32_t)k * 256 + ((uint32_t)((q >> 1) ^ (k & 7)) << 4)
                         + ((uint32_t)(q & 1) << 3);
            *(uint2*)(smem + OFF_BH + off) = make_uint2(hp0, hp1);
            *(uint2*)(smem + OFF_BL + off) = make_uint2(lp0, lp1);
        }
        ((float4*)W2s)[tid] = ((const float4*)W2)[tid];   // 1024 floats
        if (tid < HID) b1s[tid] = b1[tid];
        if (tid < NC)  b2s[tid] = b2[tid];
    }
    __syncthreads();

    // ---- per-warp constants ----
    const int cc = lane >> 2;            // class (mma2 n) / D row group
    const int kp = (lane & 3) * 2;       // col-pair base within 8-wide tiles
    const int g  = lane >> 3;            // ldmatrix address group
    const int lr = lane & 7;
    const int g1 = g & 1, g2 = g >> 1;

    // A ldmatrix lane constants
    const int arow = mi * 16 + lr + g1 * 8;
    const uint32_t a_rowoff = (uint32_t)arow * 256;
    const int asw = arow & 7;
    // B ldmatrix lane constants per ntile-pair pp (k-row swizzle index = lr)
    uint32_t bconst[4];
    #pragma unroll
    for (int pp = 0; pp < 4; pp++)
        bconst[pp] = (uint32_t)(lr + g1 * 8) * 256
                   + ((uint32_t)((ni * 8 + 2 * pp + g2) ^ lr) << 4);

    // W2 fragments (hi/lo) for mma2, precomputed once
    uint32_t w2h[4][2], w2l[4][2];
    #pragma unroll
    for (int s2 = 0; s2 < 4; s2++) {
        int j0 = ni * 64 + s2 * 16 + kp;
        split2(W2s[j0 * 8 + cc],       W2s[(j0 + 1) * 8 + cc], w2h[s2][0], w2l[s2][0]);
        split2(W2s[(j0 + 8) * 8 + cc], W2s[(j0 + 9) * 8 + cc], w2h[s2][1], w2l[s2][1]);
    }

    // ---- persistent tile loop ----
    for (int tile = blockIdx.x; tile < NT2; tile += GRID1) {
        const int node0 = tile * TM;

        // A prep: fp32 -> split bf16, swizzled [m][k]
        {
            const float4* fv = (const float4*)feats;
            #pragma unroll
            for (int r = 0; r < 8; r++) {
                int idx = tid + 256 * r;          // 0..2047
                int m = idx >> 5, q = idx & 31;
                int gn = node0 + m;
                float4 v = (gn < NN) ? fv[(size_t)gn * 32 + q]
                                     : make_float4(0.f, 0.f, 0.f, 0.f);
                uint32_t hp0, lp0, hp1, lp1;
                split2(v.x, v.y, hp0, lp0);
                split2(v.z, v.w, hp1, lp1);
                uint32_t off = (uint32_t)m * 256 + ((uint32_t)((q >> 1) ^ (m & 7)) << 4)
                             + ((uint32_t)(q & 1) << 3);
                *(uint2*)(smem + OFF_AH + off) = make_uint2(hp0, hp1);
                *(uint2*)(smem + OFF_AL + off) = make_uint2(lp0, lp1);
            }
        }
        __syncthreads();

        // ---- layer 1: 3-pass split-bf16 mma ----
        float d[8][4];
        #pragma unroll
        for (int t = 0; t < 8; t++) { d[t][0] = d[t][1] = d[t][2] = d[t][3] = 0.f; }

        #pragma unroll
        for (int p = 0; p < 3; p++) {
            const uint32_t abase = sb + (p < 2 ? OFF_AH : OFF_AL) + a_rowoff;
            const uint32_t bbase = sb + (p == 1 ? OFF_BL : OFF_BH);
            #pragma unroll
            for (int s = 0; s < 8; s++) {
                uint32_t a0, a1, a2, a3;
                ldsm4(a0, a1, a2, a3,
                      abase + ((uint32_t)((2 * s + g2) ^ asw) << 4));
                uint32_t bb[8][2];
                ldsm4t(bb[0][0], bb[0][1], bb[1][0], bb[1][1], bbase + bconst[0] + (s << 12));
                ldsm4t(bb[2][0], bb[2][1], bb[3][0], bb[3][1], bbase + bconst[1] + (s << 12));
                ldsm4t(bb[4][0], bb[4][1], bb[5][0], bb[5][1], bbase + bconst[2] + (s << 12));
                ldsm4t(bb[6][0], bb[6][1], bb[7][0], bb[7][1], bbase + bconst[3] + (s << 12));
                #pragma unroll
                for (int t = 0; t < 8; t++)
                    mma_bf16(d[t], a0, a1, a2, a3, bb[t][0], bb[t][1]);
            }
        }

        // ---- bias + relu + split (register-resident h) ----
        uint32_t hh[8][2], hl[8][2];
        #pragma unroll
        for (int t = 0; t < 8; t++) {
            int j = ni * 64 + t * 8 + kp;
            float bx = b1s[j], by = b1s[j + 1];
            float h0 = fmaxf(d[t][0] + bx, 0.f);
            float h1 = fmaxf(d[t][1] + by, 0.f);
            float h2 = fmaxf(d[t][2] + bx, 0.f);
            float h3 = fmaxf(d[t][3] + by, 0.f);
            split2(h0, h1, hh[t][0], hl[t][0]);
            split2(h2, h3, hh[t][1], hl[t][1]);
        }

        // ---- layer 2 as mma (D-frag == next A-frag lane mapping) ----
        float o[4] = {0.f, 0.f, 0.f, 0.f};
        #pragma unroll
        for (int s2 = 0; s2 < 4; s2++) {
            mma_bf16(o, hh[2*s2][0], hh[2*s2][1], hh[2*s2+1][0], hh[2*s2+1][1],
                     w2h[s2][0], w2h[s2][1]);
            mma_bf16(o, hh[2*s2][0], hh[2*s2][1], hh[2*s2+1][0], hh[2*s2+1][1],
                     w2l[s2][0], w2l[s2][1]);
            mma_bf16(o, hl[2*s2][0], hl[2*s2][1], hl[2*s2+1][0], hl[2*s2+1][1],
                     w2h[s2][0], w2h[s2][1]);
        }

        // ---- cross-ni reduction + softmax + store ----
        const int row = mi * 16 + cc;
        if (ni == 1) {
            *(float2*)(part + row * 8 + kp)       = make_float2(o[0], o[1]);
            *(float2*)(part + (row + 8) * 8 + kp) = make_float2(o[2], o[3]);
        }
        __syncthreads();
        if (ni == 0) {
            float2 p0 = *(const float2*)(part + row * 8 + kp);
            float2 p1 = *(const float2*)(part + (row + 8) * 8 + kp);
            float bx = b2s[kp], by = b2s[kp + 1];
            float x0 = o[0] + p0.x + bx, x1 = o[1] + p0.y + by;
            float x2 = o[2] + p1.x + bx, x3 = o[3] + p1.y + by;
            float m0 = fmaxf(x0, x1), m1 = fmaxf(x2, x3);
            m0 = fmaxf(m0, __shfl_xor_sync(0xffffffffu, m0, 1));
            m0 = fmaxf(m0, __shfl_xor_sync(0xffffffffu, m0, 2));
            m1 = fmaxf(m1, __shfl_xor_sync(0xffffffffu, m1, 1));
            m1 = fmaxf(m1, __shfl_xor_sync(0xffffffffu, m1, 2));
            float e0 = __expf(x0 - m0), e1 = __expf(x1 - m0);
            float e2 = __expf(x2 - m1), e3 = __expf(x3 - m1);
            float s0 = e0 + e1, s1 = e2 + e3;
            s0 += __shfl_xor_sync(0xffffffffu, s0, 1);
            s0 += __shfl_xor_sync(0xffffffffu, s0, 2);
            s1 += __shfl_xor_sync(0xffffffffu, s1, 1);
            s1 += __shfl_xor_sync(0xffffffffu, s1, 2);
            const int gn0 = node0 + row, gn1 = node0 + row + 8;
            if (gn0 < NN)
                *(float2*)(g_probs + (size_t)gn0 * NC + kp) = make_float2(e0 / s0, e1 / s0);
            if (gn1 < NN)
                *(float2*)(g_probs + (size_t)gn1 * NC + kp) = make_float2(e2 / s1, e3 / s1);
        }
        __syncthreads();   // protect part + A before next tile
    }
}

// ---------------------------------------------------------------------------
// Stage 2 (unchanged from R8, 21.2us): 4 threads/node, float2 per thread;
// 4 lanes of a node coalesce each 32B probs row; int4 index loads.
// ---------------------------------------------------------------------------
__global__ __launch_bounds__(128)
void aggregate_kernel(const int* __restrict__ nei,
                      const float* __restrict__ attention,
                      const float* __restrict__ alpha,
                      float* __restrict__ out)
{
    const int t = blockIdx.x * blockDim.x + threadIdx.x;
    const int n = t >> 2;
    const int q = t & 3;
    if (n >= NN) return;

    float a[NS];
    #pragma unroll
    for (int s = 0; s < NS; s++) a[s] = attention[n * NS + s];
    float m = a[0];
    #pragma unroll
    for (int s = 1; s < NS; s++) m = fmaxf(m, a[s]);
    float asum = 0.f;
    #pragma unroll
    for (int s = 0; s < NS; s++) { a[s] = __expf(a[s] - m); asum += a[s]; }
    const float inv_asum = 1.f / asum;

    float ax = 0.f, ay = 0.f;
    #pragma unroll
    for (int s = 0; s < NS; s++) {
        const int4* nb = (const int4*)(nei + ((size_t)s * NN + n) * NK);
        float sx = 0.f, sy = 0.f;
        #pragma unroll
        for (int i = 0; i < 4; i++) {
            const int4 id4 = __ldg(&nb[i]);
            float2 p0 = ((const float2*)(g_probs + (size_t)id4.x * NC))[q];
            float2 p1 = ((const float2*)(g_probs + (size_t)id4.y * NC))[q];
            float2 p2 = ((const float2*)(g_probs + (size_t)id4.z * NC))[q];
            float2 p3 = ((const float2*)(g_probs + (size_t)id4.w * NC))[q];
            sx += (p0.x + p1.x) + (p2.x + p3.x);
            sy += (p0.y + p1.y) + (p2.y + p3.y);
        }
        const float wgt = a[s] * inv_asum;
        ax = fmaf(wgt, sx, ax);
        ay = fmaf(wgt, sy, ay);
    }
    ax *= (1.f / (float)NK);
    ay *= (1.f / (float)NK);

    const float gg = 1.f / (1.f + __expf(-alpha[n]));
    const float2 sp = ((const float2*)(g_probs + (size_t)n * NC))[q];
    float2 o;
    o.x = gg * sp.x + (1.f - gg) * ax;
    o.y = gg * sp.y + (1.f - gg) * ay;
    ((float2*)out)[n * 4 + q] = o;
}

// ---------------------------------------------------------------------------
// Launch. Inputs: sc_nei i32[5*50000*16], feats f32[50000*128], W1 f32[128*128],
// b1 f32[128], W2 f32[128*8], b2 f32[8], alpha f32[50000], attention f32[50000*5].
// Output f32[50000*8].
// ---------------------------------------------------------------------------
extern "C" void kernel_launch(void* const* d_in, const int* in_sizes, int n_in,
                              void* d_out, int out_size)
{
    const int*   sc_nei    = (const int*)  d_in[0];
    const float* feats     = (const float*)d_in[1];
    const float* W1        = (const float*)d_in[2];
    const float* b1        = (const float*)d_in[3];
    const float* W2        = (const float*)d_in[4];
    const float* b2        = (const float*)d_in[5];
    const float* alpha     = (const float*)d_in[6];
    const float* attention = (const float*)d_in[7];
    float*       out       = (float*)d_out;

    cudaFuncSetAttribute(mlp_tc_kernel,
                         cudaFuncAttributeMaxDynamicSharedMemorySize,
                         SMEM_TOTAL);

    mlp_tc_kernel<<<GRID1, 256, SMEM_TOTAL>>>(feats, W1, b1, W2, b2);

    const int agg_threads = NN * 4;                 // 200000
    aggregate_kernel<<<(agg_threads + 127) / 128, 128>>>(sc_nei, attention, alpha, out);
}